// round 2
// baseline (speedup 1.0000x reference)
#include <cuda_runtime.h>

// ShiftedConv2d_25872882991120 — R2
//
// Analytic collapse (verified bit-exact in R1, rel_err = 0.0):
//   Reference output is all zeros except
//     out[b, c*16+s, 0, 0] = tens[b,c,127,127] * filters[s,0,0,0]
//   for each s with shifts[s] == (7,7).
//
// R1 post-mortem: one STG.128 per thread -> 16384 one-shot blocks ->
// occ 23%, issue 22%, only ~1.8 TB/s useful write BW. Fix: one block per
// output plane (4096 planes x 4096 float4), 256 threads x 16 STG.128 each,
// every iteration a contiguous coalesced 4KB warp store. Fixup element is
// always plane offset 0 -> folded into thread 0's first store.

#define PLANES     4096        // B*C*S = 8*32*16
#define PLANE_V4   4096        // 128*128 floats / 4 per float4
#define THREADS    256
#define V4_PER_THR (PLANE_V4 / THREADS)   // 16

__global__ void __launch_bounds__(THREADS)
shifted_conv_fill_kernel(const float* __restrict__ tens,
                         const float* __restrict__ filters,
                         const int*   __restrict__ shifts,
                         float4* __restrict__ out)
{
    const unsigned plane = blockIdx.x;              // 0..4095 = b*512 + c*16 + s
    float4* __restrict__ p = out + (size_t)plane * PLANE_V4 + threadIdx.x;

    const float4 z = make_float4(0.f, 0.f, 0.f, 0.f);
    float4 v0 = z;

    if (threadIdx.x == 0) {
        const unsigned s = plane & 15u;
        const int sh0 = shifts[2u * s];
        const int sh1 = shifts[2u * s + 1u];
        if (sh0 == 7 && sh1 == 7) {
            const unsigned c = (plane >> 4) & 31u;
            const unsigned b = plane >> 9;
            const unsigned n = b * 32u + c;
            v0.x = tens[(n * 128u + 127u) * 128u + 127u] * filters[s * 49u];
        }
    }

    p[0] = v0;                                  // covers the only nonzero slot
    #pragma unroll
    for (int i = 1; i < V4_PER_THR; i++)
        p[i * THREADS] = z;                     // 15 more coalesced STG.128
}

extern "C" void kernel_launch(void* const* d_in, const int* in_sizes, int n_in,
                              void* d_out, int out_size)
{
    const float* tens    = (const float*)d_in[0];
    const float* filters = (const float*)d_in[1];
    const int*   shifts  = (const int*)d_in[2];
    float4*      out     = (float4*)d_out;

    (void)in_sizes; (void)n_in; (void)out_size;

    shifted_conv_fill_kernel<<<PLANES, THREADS>>>(tens, filters, shifts, out);
}